// round 11
// baseline (speedup 1.0000x reference)
#include <cuda_runtime.h>
#include <cuda_fp16.h>
#include <stdint.h>

#define G       512
#define CDIM    512
#define TILE_M  64
#define THREADS 256
#define NCELL   64                          // 4x4x4 spatial cells
#define NMAX    50048                       // padded point capacity per batch

// ---- SMEM layout (per CTA; 2 CTAs/SM) ----
#define SM_A       0                        // 64 x 1024B, XOR-swizzled
#define SM_BBASE   65536                    // 3 slots x (32 x 512B)
#define B_STAGE_SZ 16384
#define SM_QT      (SM_BBASE + 2 * B_STAGE_SZ)            // overlaid on slot 2
#define SM_CT      (SM_QT + 8192)
#define SM_PTS     (SM_BBASE + 3 * B_STAGE_SZ)            // 114688
#define SM_MBAR    (SM_PTS + 768)                         // 6 x 8B barriers
#define SM_MASK    (SM_MBAR + 48)                         // 4B prune mask
#define SM_TOTAL   (SM_MBAR + 64)                         // 115520 (x2 = 231040)

// fp16 image of latents, K-PERMUTED: [b][k][c], row k holds lat[g=kperm(k)]
__device__ __align__(16) unsigned char g_Bprep[4ull * G * CDIM * 2];
__device__ unsigned char g_cellid[4 * NMAX];
__device__ int g_cnt[4 * NCELL];
__device__ int g_startoff[4 * NCELL];
__device__ int g_sorted[4 * NMAX];

// spatially-compact K permutation: block bk=k>>4 -> (bx,by,bz)=(bk&3,(bk>>2)&3,bk>>4)
// covering gx in {2bx,2bx+1}, gy in {2by,2by+1}, gz in {4bz..4bz+3}
__host__ __device__ __forceinline__ int kperm(int k) {
    int bk = k >> 4, i = k & 15;
    int gx = ((bk & 3) << 1) | (i & 1);
    int gy = (((bk >> 2) & 3) << 1) | ((i >> 1) & 1);
    int gz = ((bk >> 4) << 2) | (i >> 2);
    return gx * 64 + gy * 8 + gz;
}

__device__ __forceinline__ uint32_t cvta_s(const void* p) {
    return (uint32_t)__cvta_generic_to_shared(const_cast<void*>(p));
}
__device__ __forceinline__ uint32_t pack_h2(float lo, float hi) {
    __half2 h = __floats2half2_rn(lo, hi);
    return *reinterpret_cast<uint32_t*>(&h);
}
__device__ __forceinline__ void ldsm_x4(uint32_t addr, uint32_t* r) {
    asm volatile("ldmatrix.sync.aligned.m8n8.x4.shared.b16 {%0,%1,%2,%3}, [%4];"
                 : "=r"(r[0]), "=r"(r[1]), "=r"(r[2]), "=r"(r[3]) : "r"(addr));
}
__device__ __forceinline__ void ldsm_x4_t(uint32_t addr, uint32_t* r) {
    asm volatile("ldmatrix.sync.aligned.m8n8.x4.trans.shared.b16 {%0,%1,%2,%3}, [%4];"
                 : "=r"(r[0]), "=r"(r[1]), "=r"(r[2]), "=r"(r[3]) : "r"(addr));
}
__device__ __forceinline__ void mma16816(float* d, const uint32_t* a, const uint32_t* b) {
    asm volatile(
        "mma.sync.aligned.m16n8k16.row.col.f32.f16.f16.f32 "
        "{%0,%1,%2,%3}, {%4,%5,%6,%7}, {%8,%9}, {%0,%1,%2,%3};"
        : "+f"(d[0]), "+f"(d[1]), "+f"(d[2]), "+f"(d[3])
        : "r"(a[0]), "r"(a[1]), "r"(a[2]), "r"(a[3]), "r"(b[0]), "r"(b[1]));
}
__device__ __forceinline__ void mbar_wait(uint32_t addr, uint32_t parity) {
    asm volatile(
        "{\n\t.reg .pred P;\n\t"
        "W_%=:\n\t"
        "mbarrier.try_wait.parity.acquire.cta.shared::cta.b64 P, [%0], %1, 0x989680;\n\t"
        "@!P bra W_%=;\n\t}"
        :: "r"(addr), "r"(parity) : "memory");
}
__device__ __forceinline__ void mbar_init(uint32_t addr, uint32_t cnt) {
    asm volatile("mbarrier.init.shared.b64 [%0], %1;" :: "r"(addr), "r"(cnt) : "memory");
}
__device__ __forceinline__ void mbar_arrive(uint32_t addr) {
    asm volatile("mbarrier.arrive.shared.b64 _, [%0];" :: "r"(addr) : "memory");
}
__device__ __forceinline__ void cpasync_arrive_noinc(uint32_t addr) {
    asm volatile("cp.async.mbarrier.arrive.noinc.shared::cta.b64 [%0];"
                 :: "r"(addr) : "memory");
}

// ---------- prep: permuted fp32 -> fp16 latents image ----------
__global__ void rbf_prep(const float* __restrict__ lat) {
    int k = blockIdx.x, b = blockIdx.y;
    int gp = kperm(k);
    const float* src = lat + ((size_t)b * G + gp) * CDIM;
    uint32_t* dst = (uint32_t*)(g_Bprep + ((size_t)b * G + k) * (CDIM * 2));
    int c2 = threadIdx.x;                   // 0..255
    dst[c2] = pack_h2(src[2 * c2], src[2 * c2 + 1]);
}

// ---------- sort pipeline (deterministic) ----------
__global__ void rbf_zero() {
    int i = threadIdx.x;
    if (i < 4 * NCELL) g_cnt[i] = 0;
}

__global__ void rbf_cell(const float* __restrict__ pts, int N) {
    int i = blockIdx.x * blockDim.x + threadIdx.x;
    if (i >= 4 * N) return;
    int b = i / N, n = i - b * N;
    const float* p = pts + (size_t)i * 3;
    int cx = min(3, max(0, (int)((p[0] + 1.0f) * 2.0f)));
    int cy = min(3, max(0, (int)((p[1] + 1.0f) * 2.0f)));
    int cz = min(3, max(0, (int)((p[2] + 1.0f) * 2.0f)));
    int cell = cx | (cy << 2) | (cz << 4);
    g_cellid[b * NMAX + n] = (unsigned char)cell;
    atomicAdd(&g_cnt[b * NCELL + cell], 1);
}

__global__ void rbf_scan() {
    int b = threadIdx.x;                    // 4 threads
    if (b >= 4) return;
    int run = 0;
    for (int c = 0; c < NCELL; ++c) {
        g_startoff[b * NCELL + c] = run;
        run += g_cnt[b * NCELL + c];
    }
}

// stable compaction: CTA per (cell, batch); preserves ascending n within cell
__global__ void rbf_compact(int N) {
    int cell = blockIdx.x, b = blockIdx.y;
    int tid = threadIdx.x, wid = tid >> 5, lane = tid & 31;
    __shared__ int cursor;
    __shared__ int wcnt[8];
    if (tid == 0) cursor = 0;
    __syncthreads();
    int base = g_startoff[b * NCELL + cell];
    const unsigned char* cl = g_cellid + b * NMAX;
    int* dst = g_sorted + b * NMAX;
    for (int s = 0; s < N; s += THREADS) {
        int n = s + tid;
        bool m = (n < N) && (cl[n] == (unsigned char)cell);
        unsigned bal = __ballot_sync(0xFFFFFFFFu, m);
        if (lane == 0) wcnt[wid] = __popc(bal);
        __syncthreads();
        int woff = 0;
        #pragma unroll
        for (int w = 0; w < 8; ++w) woff += (w < wid) ? wcnt[w] : 0;
        if (m)
            dst[base + cursor + woff + __popc(bal & ((1u << lane) - 1u))] = n;
        __syncthreads();
        if (tid == 0) {
            int t = 0;
            #pragma unroll
            for (int w = 0; w < 8; ++w) t += wcnt[w];
            cursor += t;
        }
        __syncthreads();
    }
}

// ---------- main kernel ----------
__global__ void __launch_bounds__(THREADS, 2)
rbf_main(const float* __restrict__ points, const float* __restrict__ eps,
         float* __restrict__ out, int Ntot)
{
    extern __shared__ __align__(1024) unsigned char smem[];
    const uint32_t sbase = cvta_s(smem);
    const int tid  = threadIdx.x;
    const int wid  = tid >> 5;
    const int lane = tid & 31;
    const int b    = blockIdx.y;
    const int n0   = blockIdx.x * TILE_M;
    const unsigned char* Bsrc = g_Bprep + (size_t)b * (G * CDIM * 2);
    const int* sIdx = g_sorted + b * NMAX;

    const uint32_t mb_full  = sbase + SM_MBAR;
    const uint32_t mb_empty = sbase + SM_MBAR + 24;

    if (tid == 0) {
        #pragma unroll
        for (int s = 0; s < 3; ++s) {
            mbar_init(mb_full + s * 8, THREADS);
            mbar_init(mb_empty + s * 8, 8);
        }
    }
    __syncthreads();

    auto issue_slice = [&](int g) {
        uint32_t dstbase = sbase + SM_BBASE + (uint32_t)(g % 3) * B_STAGE_SZ;
        int cc = g >> 4;
        #pragma unroll
        for (int j = 0; j < 4; ++j) {
            int s  = tid + j * THREADS;
            int r  = s >> 5;
            int ch = s & 31;
            const unsigned char* src = Bsrc
                + ((size_t)(((g & 15) * 32) + r) * CDIM + cc * 256) * 2 + ch * 16;
            uint32_t dst = dstbase + r * 512 + (uint32_t)((ch ^ (r & 7)) << 4);
            asm volatile("cp.async.cg.shared.global [%0], [%1], 16;" :: "r"(dst), "l"(src));
        }
    };

    // slices 0 and 1 issued unconditionally (mask not ready yet)
    issue_slice(0); cpasync_arrive_noinc(mb_full + 0);
    issue_slice(1); cpasync_arrive_noinc(mb_full + 8);

    // stage gathered points
    {
        float* stage = (float*)(smem + SM_PTS);
        for (int i = tid; i < TILE_M; i += THREADS) {
            int n = n0 + i;
            float x = 0.f, y = 0.f, z = 0.f;
            if (n < Ntot) {
                int o = sIdx[n];
                const float* p = points + ((size_t)b * Ntot + o) * 3;
                x = p[0]; y = p[1]; z = p[2];
            }
            stage[i * 3 + 0] = x; stage[i * 3 + 1] = y; stage[i * 3 + 2] = z;
        }
    }

    // per-k tables, K-PERMUTED (overlaid on slot-2 buffer)
    {
        float4* qt = (float4*)(smem + SM_QT);
        float*  ct = (float*)(smem + SM_CT);
        const float LOG2E = 1.4426950408889634f;
        const float step  = 2.0f / 7.0f;
        for (int k = tid; k < G; k += THREADS) {
            int gp = kperm(k);
            float gx = -1.0f + step * (float)(gp >> 6);
            float gy = -1.0f + step * (float)((gp >> 3) & 7);
            float gz = -1.0f + step * (float)(gp & 7);
            float e  = eps[gp];
            float s  = -e * e * LOG2E;
            qt[k] = make_float4(-2.0f * s * gx, -2.0f * s * gy, -2.0f * s * gz, s);
            ct[k] = s * (gx * gx + gy * gy + gz * gz);
        }
    }
    __syncthreads();

    // warp 0: tile bbox + per-block prune mask (32 blocks of 16 k)
    if (wid == 0) {
        const float* stage = (const float*)(smem + SM_PTS);
        float lx = 1e9f, ly = 1e9f, lz = 1e9f, hx = -1e9f, hy = -1e9f, hz = -1e9f;
        for (int i = lane; i < TILE_M; i += 32) {
            float x = stage[i * 3 + 0], y = stage[i * 3 + 1], z = stage[i * 3 + 2];
            lx = fminf(lx, x); hx = fmaxf(hx, x);
            ly = fminf(ly, y); hy = fmaxf(hy, y);
            lz = fminf(lz, z); hz = fmaxf(hz, z);
        }
        #pragma unroll
        for (int o = 16; o; o >>= 1) {
            lx = fminf(lx, __shfl_xor_sync(0xFFFFFFFFu, lx, o));
            ly = fminf(ly, __shfl_xor_sync(0xFFFFFFFFu, ly, o));
            lz = fminf(lz, __shfl_xor_sync(0xFFFFFFFFu, lz, o));
            hx = fmaxf(hx, __shfl_xor_sync(0xFFFFFFFFu, hx, o));
            hy = fmaxf(hy, __shfl_xor_sync(0xFFFFFFFFu, hy, o));
            hz = fmaxf(hz, __shfl_xor_sync(0xFFFFFFFFu, hz, o));
        }
        const float4* qt = (const float4*)(smem + SM_QT);
        const float step = 2.0f / 7.0f;
        int bk = lane;
        float maxS = -1e30f;
        #pragma unroll
        for (int i = 0; i < 16; ++i) maxS = fmaxf(maxS, qt[bk * 16 + i].w);
        float bx0 = -1.0f + step * (float)(2 * (bk & 3)),        bx1 = bx0 + step;
        float by0 = -1.0f + step * (float)(2 * ((bk >> 2) & 3)), by1 = by0 + step;
        float bz0 = -1.0f + step * (float)(4 * (bk >> 4)),       bz1 = bz0 + 3.0f * step;
        float dx = fmaxf(0.0f, fmaxf(lx - bx1, bx0 - hx));
        float dy = fmaxf(0.0f, fmaxf(ly - by1, by0 - hy));
        float dz = fmaxf(0.0f, fmaxf(lz - bz1, bz0 - hz));
        float d2 = dx * dx + dy * dy + dz * dz;
        bool keep = (d2 * maxS) >= -17.0f;     // drop only if max weight < 2^-17
        unsigned m = __ballot_sync(0xFFFFFFFFu, keep);
        if (lane == 0) *(unsigned*)(smem + SM_MASK) = m;
    }
    __syncthreads();
    const unsigned mask = *(const unsigned*)(smem + SM_MASK);

    // A-gen with block skip: thread -> (row = tid&63, kq = tid>>6), 128 k
    {
        const int row   = tid & 63;
        const int kbase = (tid >> 6) * 128;
        const float* stage = (const float*)(smem + SM_PTS);
        float px = stage[row * 3 + 0], py = stage[row * 3 + 1], pz = stage[row * 3 + 2];
        float p2 = px * px + py * py + pz * pz;
        const float4* qt = (const float4*)(smem + SM_QT);
        const float*  ct = (const float*)(smem + SM_CT);
        const uint32_t arow = sbase + SM_A + (uint32_t)row * 1024;
        const int swz = row & 7;
        #pragma unroll 4
        for (int j = 0; j < 16; ++j) {
            int k0 = kbase + j * 8;
            if (!((mask >> (k0 >> 4)) & 1u)) continue;       // warp-uniform
            float ev[8];
            #pragma unroll
            for (int q = 0; q < 8; ++q) {
                int k = k0 + q;
                float4 qv = qt[k];
                float arg = fmaf(qv.x, px, fmaf(qv.y, py,
                            fmaf(qv.z, pz, fmaf(qv.w, p2, ct[k]))));
                asm("ex2.approx.f32 %0, %1;" : "=f"(ev[q]) : "f"(arg));
            }
            uint4 pk;
            pk.x = pack_h2(ev[0], ev[1]);
            pk.y = pack_h2(ev[2], ev[3]);
            pk.z = pack_h2(ev[4], ev[5]);
            pk.w = pack_h2(ev[6], ev[7]);
            int cj = k0 >> 3;
            asm volatile("st.shared.v4.b32 [%0], {%1,%2,%3,%4};"
                         :: "r"(arow + (uint32_t)((cj ^ swz) << 4)),
                            "r"(pk.x), "r"(pk.y), "r"(pk.z), "r"(pk.w));
        }
    }
    __syncthreads();

    const int wm = (wid & 1) * 32;
    const int wn = (wid >> 1) * 64;
    const int hi = lane >> 4;

    uint32_t Abase[2], AswzX[2];
    #pragma unroll
    for (int tm = 0; tm < 2; ++tm) {
        int row = wm + tm * 16 + (lane & 15);
        Abase[tm] = sbase + SM_A + (uint32_t)row * 1024;
        AswzX[tm] = (uint32_t)(row & 7);
    }
    uint32_t Boff[2][4];
    #pragma unroll
    for (int kk = 0; kk < 2; ++kk)
        #pragma unroll
        for (int tn2 = 0; tn2 < 4; ++tn2) {
            int rr   = kk * 16 + (lane & 15);
            int colc = (wn + tn2 * 16 + hi * 8) >> 3;
            Boff[kk][tn2] = (uint32_t)rr * 512 + (uint32_t)((colc ^ (rr & 7)) << 4);
        }

    float acc[2][8][4];
    #pragma unroll
    for (int tm = 0; tm < 2; ++tm)
        #pragma unroll
        for (int tn = 0; tn < 8; ++tn)
            #pragma unroll
            for (int q = 0; q < 4; ++q)
                acc[tm][tn][q] = 0.0f;

    for (int g = 0; g < 32; ++g) {
        const int slot = g % 3;
        mbar_wait(mb_full + slot * 8, (uint32_t)((g / 3) & 1));

        // slice g covers k-blocks 2*(g&15), 2*(g&15)+1  (FIX: mask by g&15, not g)
        const unsigned mk = (mask >> (2 * (g & 15))) & 3u;
        if (mk) {
            uint32_t Bb = sbase + SM_BBASE + (uint32_t)slot * B_STAGE_SZ;
            uint32_t c0 = (uint32_t)((g & 15) * 4 + hi);
            #pragma unroll
            for (int kk = 0; kk < 2; ++kk) {
                if (!((mk >> kk) & 1u)) continue;
                uint32_t af[2][4];
                #pragma unroll
                for (int tm = 0; tm < 2; ++tm)
                    ldsm_x4(Abase[tm] + (((c0 + kk * 2) ^ AswzX[tm]) << 4), af[tm]);
                uint32_t bf[4][4];
                #pragma unroll
                for (int tn2 = 0; tn2 < 4; ++tn2)
                    ldsm_x4_t(Bb + Boff[kk][tn2], bf[tn2]);
                #pragma unroll
                for (int tm = 0; tm < 2; ++tm)
                    #pragma unroll
                    for (int tn = 0; tn < 8; ++tn)
                        mma16816(acc[tm][tn], af[tm], &bf[tn >> 1][(tn & 1) * 2]);
            }
        }

        if (lane == 0) mbar_arrive(mb_empty + slot * 8);

        if (g + 2 < 32) {
            if (g >= 1)
                mbar_wait(mb_empty + ((g - 1) % 3) * 8, (uint32_t)(((g - 1) / 3) & 1));
            if ((mask >> (2 * ((g + 2) & 15))) & 3u)       // FIX: mask by (g+2)&15
                issue_slice(g + 2);
            cpasync_arrive_noinc(mb_full + ((g + 2) % 3) * 8);
        }

        if (g == 15 || g == 31) {
            int cc = g >> 4;
            #pragma unroll
            for (int tm = 0; tm < 2; ++tm) {
                int rbase = n0 + wm + tm * 16 + (lane >> 2);
                #pragma unroll
                for (int half = 0; half < 2; ++half) {
                    int r = rbase + half * 8;
                    if (r < Ntot) {
                        int orig = sIdx[r];
                        float* op = out + ((size_t)b * Ntot + orig) * CDIM
                                    + cc * 256 + wn + (lane & 3) * 2;
                        #pragma unroll
                        for (int tn = 0; tn < 8; ++tn) {
                            float2 v = make_float2(acc[tm][tn][half * 2],
                                                   acc[tm][tn][half * 2 + 1]);
                            *reinterpret_cast<float2*>(op + tn * 8) = v;
                        }
                    }
                }
            }
            if (g == 15) {
                #pragma unroll
                for (int tm = 0; tm < 2; ++tm)
                    #pragma unroll
                    for (int tn = 0; tn < 8; ++tn)
                        #pragma unroll
                        for (int q = 0; q < 4; ++q)
                            acc[tm][tn][q] = 0.0f;
            }
        }
    }
}

extern "C" void kernel_launch(void* const* d_in, const int* in_sizes, int n_in,
                              void* d_out, int out_size) {
    const float* points = (const float*)d_in[0];
    const float* lat    = (const float*)d_in[1];
    const float* eps    = (const float*)d_in[2];
    float* out = (float*)d_out;

    int B = in_sizes[1] / (G * CDIM);          // 4
    int N = in_sizes[0] / (3 * B);             // 50000

    cudaFuncSetAttribute(rbf_main, cudaFuncAttributeMaxDynamicSharedMemorySize, SM_TOTAL);

    rbf_prep<<<dim3(G, B), 256>>>(lat);
    rbf_zero<<<1, 256>>>();
    rbf_cell<<<(4 * N + 255) / 256, 256>>>(points, N);
    rbf_scan<<<1, 4>>>();
    rbf_compact<<<dim3(NCELL, B), THREADS>>>(N);
    rbf_main<<<dim3((N + TILE_M - 1) / TILE_M, B), THREADS, SM_TOTAL>>>(points, eps, out, N);
}

// round 12
// speedup vs baseline: 1.2671x; 1.2671x over previous
#include <cuda_runtime.h>
#include <cuda_fp16.h>
#include <stdint.h>

#define G       512
#define CDIM    512
#define TILE_M  64
#define THREADS 256
#define NCELL   64                          // 4x4x4 spatial cells
#define NMAX    50048                       // padded point capacity per batch
#define CHCAP   200                         // max 256-pt chunks per batch

// ---- SMEM layout (per CTA; 2 CTAs/SM) ----
#define SM_A       0                        // 64 x 1024B, XOR-swizzled
#define SM_BBASE   65536                    // 3 slots x (32 x 512B)
#define B_STAGE_SZ 16384
#define SM_QT      (SM_BBASE + 2 * B_STAGE_SZ)            // overlaid on slot 2
#define SM_CT      (SM_QT + 8192)
#define SM_PTS     (SM_BBASE + 3 * B_STAGE_SZ)            // 114688
#define SM_MBAR    (SM_PTS + 768)                         // 6 x 8B barriers
#define SM_MASK    (SM_MBAR + 48)                         // 4B prune mask
#define SM_TOTAL   (SM_MBAR + 64)                         // 115520 (x2 = 231040)

// fp16 image of latents, K-PERMUTED: [b][k][c], row k holds lat[g=kperm(k)]
__device__ __align__(16) unsigned char g_Bprep[4ull * G * CDIM * 2];
__device__ unsigned char g_cellid[4 * NMAX];
__device__ int g_ccnt[4 * CHCAP * NCELL];
__device__ int g_coff[4 * CHCAP * NCELL];
__device__ int g_cellbase[4 * NCELL];
__device__ int g_sorted[4 * NMAX];

// spatially-compact K permutation: block bk=k>>4 -> (bx,by,bz)=(bk&3,(bk>>2)&3,bk>>4)
__host__ __device__ __forceinline__ int kperm(int k) {
    int bk = k >> 4, i = k & 15;
    int gx = ((bk & 3) << 1) | (i & 1);
    int gy = (((bk >> 2) & 3) << 1) | ((i >> 1) & 1);
    int gz = ((bk >> 4) << 2) | (i >> 2);
    return gx * 64 + gy * 8 + gz;
}

__device__ __forceinline__ uint32_t cvta_s(const void* p) {
    return (uint32_t)__cvta_generic_to_shared(const_cast<void*>(p));
}
__device__ __forceinline__ uint32_t pack_h2(float lo, float hi) {
    __half2 h = __floats2half2_rn(lo, hi);
    return *reinterpret_cast<uint32_t*>(&h);
}
__device__ __forceinline__ void ldsm_x4(uint32_t addr, uint32_t* r) {
    asm volatile("ldmatrix.sync.aligned.m8n8.x4.shared.b16 {%0,%1,%2,%3}, [%4];"
                 : "=r"(r[0]), "=r"(r[1]), "=r"(r[2]), "=r"(r[3]) : "r"(addr));
}
__device__ __forceinline__ void ldsm_x4_t(uint32_t addr, uint32_t* r) {
    asm volatile("ldmatrix.sync.aligned.m8n8.x4.trans.shared.b16 {%0,%1,%2,%3}, [%4];"
                 : "=r"(r[0]), "=r"(r[1]), "=r"(r[2]), "=r"(r[3]) : "r"(addr));
}
__device__ __forceinline__ void mma16816(float* d, const uint32_t* a, const uint32_t* b) {
    asm volatile(
        "mma.sync.aligned.m16n8k16.row.col.f32.f16.f16.f32 "
        "{%0,%1,%2,%3}, {%4,%5,%6,%7}, {%8,%9}, {%0,%1,%2,%3};"
        : "+f"(d[0]), "+f"(d[1]), "+f"(d[2]), "+f"(d[3])
        : "r"(a[0]), "r"(a[1]), "r"(a[2]), "r"(a[3]), "r"(b[0]), "r"(b[1]));
}
__device__ __forceinline__ void mbar_wait(uint32_t addr, uint32_t parity) {
    asm volatile(
        "{\n\t.reg .pred P;\n\t"
        "W_%=:\n\t"
        "mbarrier.try_wait.parity.acquire.cta.shared::cta.b64 P, [%0], %1, 0x989680;\n\t"
        "@!P bra W_%=;\n\t}"
        :: "r"(addr), "r"(parity) : "memory");
}
__device__ __forceinline__ void mbar_init(uint32_t addr, uint32_t cnt) {
    asm volatile("mbarrier.init.shared.b64 [%0], %1;" :: "r"(addr), "r"(cnt) : "memory");
}
__device__ __forceinline__ void mbar_arrive(uint32_t addr) {
    asm volatile("mbarrier.arrive.shared.b64 _, [%0];" :: "r"(addr) : "memory");
}
__device__ __forceinline__ void cpasync_arrive_noinc(uint32_t addr) {
    asm volatile("cp.async.mbarrier.arrive.noinc.shared::cta.b64 [%0];"
                 :: "r"(addr) : "memory");
}

// ---------- prep: permuted fp32 -> fp16 latents image ----------
__global__ void rbf_prep(const float* __restrict__ lat) {
    int k = blockIdx.x, b = blockIdx.y;
    int gp = kperm(k);
    const float* src = lat + ((size_t)b * G + gp) * CDIM;
    uint32_t* dst = (uint32_t*)(g_Bprep + ((size_t)b * G + k) * (CDIM * 2));
    int c2 = threadIdx.x;
    dst[c2] = pack_h2(src[2 * c2], src[2 * c2 + 1]);
}

// ---------- sort: phase 1 — cell ids + per-chunk histograms ----------
__global__ void rbf_histo(const float* __restrict__ pts, int N) {
    int ch = blockIdx.x, b = blockIdx.y, tid = threadIdx.x;
    __shared__ int cnt[NCELL];
    if (tid < NCELL) cnt[tid] = 0;
    __syncthreads();
    int n = ch * 256 + tid;
    if (n < N) {
        const float* p = pts + ((size_t)b * N + n) * 3;
        int cx = min(3, max(0, (int)((p[0] + 1.0f) * 2.0f)));
        int cy = min(3, max(0, (int)((p[1] + 1.0f) * 2.0f)));
        int cz = min(3, max(0, (int)((p[2] + 1.0f) * 2.0f)));
        int cell = cx | (cy << 2) | (cz << 4);
        g_cellid[b * NMAX + n] = (unsigned char)cell;
        atomicAdd(&cnt[cell], 1);
    }
    __syncthreads();
    if (tid < NCELL) g_ccnt[(b * CHCAP + ch) * NCELL + tid] = cnt[tid];
}

// ---------- sort: phase 2 — per-cell chunk prefix + cell bases ----------
__global__ void rbf_off(int NCH) {
    int b = blockIdx.x, c = threadIdx.x;            // 64 threads
    __shared__ int tot[NCELL];
    int run = 0;
    for (int ch = 0; ch < NCH; ++ch) {
        int idx = (b * CHCAP + ch) * NCELL + c;
        int t = g_ccnt[idx];
        g_coff[idx] = run;
        run += t;
    }
    tot[c] = run;
    __syncthreads();
    if (c == 0) {
        int acc = 0;
        for (int i = 0; i < NCELL; ++i) { int t = tot[i]; tot[i] = acc; acc += t; }
    }
    __syncthreads();
    g_cellbase[b * NCELL + c] = tot[c];
}

// ---------- sort: phase 3 — stable scatter (deterministic: order = n order) ----------
__global__ void rbf_scatter(int N) {
    int ch = blockIdx.x, b = blockIdx.y, tid = threadIdx.x;
    int wid = tid >> 5, lane = tid & 31;
    __shared__ int cur[NCELL];
    if (tid < NCELL)
        cur[tid] = g_coff[(b * CHCAP + ch) * NCELL + tid] + g_cellbase[b * NCELL + tid];
    __syncthreads();
    int n = ch * 256 + tid;
    int mycell = (n < N) ? (int)g_cellid[b * NMAX + n] : NCELL;
    #pragma unroll
    for (int w = 0; w < 8; ++w) {                    // warps in tid order -> stable
        if (wid == w) {
            unsigned mm = __match_any_sync(0xFFFFFFFFu, mycell);
            int leader = __ffs(mm) - 1;
            int rank = __popc(mm & ((1u << lane) - 1u));
            int base = 0;
            if (lane == leader && mycell < NCELL)
                base = atomicAdd(&cur[mycell], __popc(mm));
            base = __shfl_sync(0xFFFFFFFFu, base, leader);
            if (mycell < NCELL)
                g_sorted[b * NMAX + base + rank] = n;
        }
        __syncthreads();
    }
}

// ---------- main kernel ----------
__global__ void __launch_bounds__(THREADS, 2)
rbf_main(const float* __restrict__ points, const float* __restrict__ eps,
         float* __restrict__ out, int Ntot)
{
    extern __shared__ __align__(1024) unsigned char smem[];
    const uint32_t sbase = cvta_s(smem);
    const int tid  = threadIdx.x;
    const int wid  = tid >> 5;
    const int lane = tid & 31;
    const int b    = blockIdx.y;
    const int n0   = blockIdx.x * TILE_M;
    const unsigned char* Bsrc = g_Bprep + (size_t)b * (G * CDIM * 2);
    const int* sIdx = g_sorted + b * NMAX;

    const uint32_t mb_full  = sbase + SM_MBAR;
    const uint32_t mb_empty = sbase + SM_MBAR + 24;

    if (tid == 0) {
        #pragma unroll
        for (int s = 0; s < 3; ++s) {
            mbar_init(mb_full + s * 8, THREADS);
            mbar_init(mb_empty + s * 8, 8);
        }
    }
    __syncthreads();

    auto issue_slice = [&](int g) {
        uint32_t dstbase = sbase + SM_BBASE + (uint32_t)(g % 3) * B_STAGE_SZ;
        int cc = g >> 4;
        #pragma unroll
        for (int j = 0; j < 4; ++j) {
            int s  = tid + j * THREADS;
            int r  = s >> 5;
            int ch = s & 31;
            const unsigned char* src = Bsrc
                + ((size_t)(((g & 15) * 32) + r) * CDIM + cc * 256) * 2 + ch * 16;
            uint32_t dst = dstbase + r * 512 + (uint32_t)((ch ^ (r & 7)) << 4);
            asm volatile("cp.async.cg.shared.global [%0], [%1], 16;" :: "r"(dst), "l"(src));
        }
    };

    issue_slice(0); cpasync_arrive_noinc(mb_full + 0);
    issue_slice(1); cpasync_arrive_noinc(mb_full + 8);

    // stage gathered points
    {
        float* stage = (float*)(smem + SM_PTS);
        for (int i = tid; i < TILE_M; i += THREADS) {
            int n = n0 + i;
            float x = 0.f, y = 0.f, z = 0.f;
            if (n < Ntot) {
                int o = sIdx[n];
                const float* p = points + ((size_t)b * Ntot + o) * 3;
                x = p[0]; y = p[1]; z = p[2];
            }
            stage[i * 3 + 0] = x; stage[i * 3 + 1] = y; stage[i * 3 + 2] = z;
        }
    }

    // per-k tables, K-PERMUTED (overlaid on slot-2 buffer)
    {
        float4* qt = (float4*)(smem + SM_QT);
        float*  ct = (float*)(smem + SM_CT);
        const float LOG2E = 1.4426950408889634f;
        const float step  = 2.0f / 7.0f;
        for (int k = tid; k < G; k += THREADS) {
            int gp = kperm(k);
            float gx = -1.0f + step * (float)(gp >> 6);
            float gy = -1.0f + step * (float)((gp >> 3) & 7);
            float gz = -1.0f + step * (float)(gp & 7);
            float e  = eps[gp];
            float s  = -e * e * LOG2E;
            qt[k] = make_float4(-2.0f * s * gx, -2.0f * s * gy, -2.0f * s * gz, s);
            ct[k] = s * (gx * gx + gy * gy + gz * gz);
        }
    }
    __syncthreads();

    // warp 0: tile bbox + per-block prune mask (32 blocks of 16 k)
    if (wid == 0) {
        const float* stage = (const float*)(smem + SM_PTS);
        float lx = 1e9f, ly = 1e9f, lz = 1e9f, hx = -1e9f, hy = -1e9f, hz = -1e9f;
        for (int i = lane; i < TILE_M; i += 32) {
            float x = stage[i * 3 + 0], y = stage[i * 3 + 1], z = stage[i * 3 + 2];
            lx = fminf(lx, x); hx = fmaxf(hx, x);
            ly = fminf(ly, y); hy = fmaxf(hy, y);
            lz = fminf(lz, z); hz = fmaxf(hz, z);
        }
        #pragma unroll
        for (int o = 16; o; o >>= 1) {
            lx = fminf(lx, __shfl_xor_sync(0xFFFFFFFFu, lx, o));
            ly = fminf(ly, __shfl_xor_sync(0xFFFFFFFFu, ly, o));
            lz = fminf(lz, __shfl_xor_sync(0xFFFFFFFFu, lz, o));
            hx = fmaxf(hx, __shfl_xor_sync(0xFFFFFFFFu, hx, o));
            hy = fmaxf(hy, __shfl_xor_sync(0xFFFFFFFFu, hy, o));
            hz = fmaxf(hz, __shfl_xor_sync(0xFFFFFFFFu, hz, o));
        }
        const float4* qt = (const float4*)(smem + SM_QT);
        const float step = 2.0f / 7.0f;
        int bk = lane;
        float maxS = -1e30f;
        #pragma unroll
        for (int i = 0; i < 16; ++i) maxS = fmaxf(maxS, qt[bk * 16 + i].w);
        float bx0 = -1.0f + step * (float)(2 * (bk & 3)),        bx1 = bx0 + step;
        float by0 = -1.0f + step * (float)(2 * ((bk >> 2) & 3)), by1 = by0 + step;
        float bz0 = -1.0f + step * (float)(4 * (bk >> 4)),       bz1 = bz0 + 3.0f * step;
        float dx = fmaxf(0.0f, fmaxf(lx - bx1, bx0 - hx));
        float dy = fmaxf(0.0f, fmaxf(ly - by1, by0 - hy));
        float dz = fmaxf(0.0f, fmaxf(lz - bz1, bz0 - hz));
        float d2 = dx * dx + dy * dy + dz * dz;
        bool keep = (d2 * maxS) >= -15.0f;     // drop only if max weight < 2^-15
        unsigned m = __ballot_sync(0xFFFFFFFFu, keep);
        if (lane == 0) *(unsigned*)(smem + SM_MASK) = m;
    }
    __syncthreads();
    const unsigned mask = *(const unsigned*)(smem + SM_MASK);

    // A-gen with block skip
    {
        const int row   = tid & 63;
        const int kbase = (tid >> 6) * 128;
        const float* stage = (const float*)(smem + SM_PTS);
        float px = stage[row * 3 + 0], py = stage[row * 3 + 1], pz = stage[row * 3 + 2];
        float p2 = px * px + py * py + pz * pz;
        const float4* qt = (const float4*)(smem + SM_QT);
        const float*  ct = (const float*)(smem + SM_CT);
        const uint32_t arow = sbase + SM_A + (uint32_t)row * 1024;
        const int swz = row & 7;
        #pragma unroll 4
        for (int j = 0; j < 16; ++j) {
            int k0 = kbase + j * 8;
            if (!((mask >> (k0 >> 4)) & 1u)) continue;
            float ev[8];
            #pragma unroll
            for (int q = 0; q < 8; ++q) {
                int k = k0 + q;
                float4 qv = qt[k];
                float arg = fmaf(qv.x, px, fmaf(qv.y, py,
                            fmaf(qv.z, pz, fmaf(qv.w, p2, ct[k]))));
                asm("ex2.approx.f32 %0, %1;" : "=f"(ev[q]) : "f"(arg));
            }
            uint4 pk;
            pk.x = pack_h2(ev[0], ev[1]);
            pk.y = pack_h2(ev[2], ev[3]);
            pk.z = pack_h2(ev[4], ev[5]);
            pk.w = pack_h2(ev[6], ev[7]);
            int cj = k0 >> 3;
            asm volatile("st.shared.v4.b32 [%0], {%1,%2,%3,%4};"
                         :: "r"(arow + (uint32_t)((cj ^ swz) << 4)),
                            "r"(pk.x), "r"(pk.y), "r"(pk.z), "r"(pk.w));
        }
    }
    __syncthreads();

    const int wm = (wid & 1) * 32;
    const int wn = (wid >> 1) * 64;
    const int hi = lane >> 4;

    uint32_t Abase[2], AswzX[2];
    #pragma unroll
    for (int tm = 0; tm < 2; ++tm) {
        int row = wm + tm * 16 + (lane & 15);
        Abase[tm] = sbase + SM_A + (uint32_t)row * 1024;
        AswzX[tm] = (uint32_t)(row & 7);
    }
    uint32_t Boff[2][4];
    #pragma unroll
    for (int kk = 0; kk < 2; ++kk)
        #pragma unroll
        for (int tn2 = 0; tn2 < 4; ++tn2) {
            int rr   = kk * 16 + (lane & 15);
            int colc = (wn + tn2 * 16 + hi * 8) >> 3;
            Boff[kk][tn2] = (uint32_t)rr * 512 + (uint32_t)((colc ^ (rr & 7)) << 4);
        }

    float acc[2][8][4];
    #pragma unroll
    for (int tm = 0; tm < 2; ++tm)
        #pragma unroll
        for (int tn = 0; tn < 8; ++tn)
            #pragma unroll
            for (int q = 0; q < 4; ++q)
                acc[tm][tn][q] = 0.0f;

    for (int g = 0; g < 32; ++g) {
        const int slot = g % 3;
        mbar_wait(mb_full + slot * 8, (uint32_t)((g / 3) & 1));

        const unsigned mk = (mask >> (2 * (g & 15))) & 3u;
        if (mk) {
            uint32_t Bb = sbase + SM_BBASE + (uint32_t)slot * B_STAGE_SZ;
            uint32_t c0 = (uint32_t)((g & 15) * 4 + hi);
            #pragma unroll
            for (int kk = 0; kk < 2; ++kk) {
                if (!((mk >> kk) & 1u)) continue;
                uint32_t af[2][4];
                #pragma unroll
                for (int tm = 0; tm < 2; ++tm)
                    ldsm_x4(Abase[tm] + (((c0 + kk * 2) ^ AswzX[tm]) << 4), af[tm]);
                uint32_t bf[4][4];
                #pragma unroll
                for (int tn2 = 0; tn2 < 4; ++tn2)
                    ldsm_x4_t(Bb + Boff[kk][tn2], bf[tn2]);
                #pragma unroll
                for (int tm = 0; tm < 2; ++tm)
                    #pragma unroll
                    for (int tn = 0; tn < 8; ++tn)
                        mma16816(acc[tm][tn], af[tm], &bf[tn >> 1][(tn & 1) * 2]);
            }
        }

        if (lane == 0) mbar_arrive(mb_empty + slot * 8);

        if (g + 2 < 32) {
            if (g >= 1)
                mbar_wait(mb_empty + ((g - 1) % 3) * 8, (uint32_t)(((g - 1) / 3) & 1));
            if ((mask >> (2 * ((g + 2) & 15))) & 3u)
                issue_slice(g + 2);
            cpasync_arrive_noinc(mb_full + ((g + 2) % 3) * 8);
        }

        if (g == 15 || g == 31) {
            int cc = g >> 4;
            #pragma unroll
            for (int tm = 0; tm < 2; ++tm) {
                int rbase = n0 + wm + tm * 16 + (lane >> 2);
                #pragma unroll
                for (int half = 0; half < 2; ++half) {
                    int r = rbase + half * 8;
                    if (r < Ntot) {
                        int orig = sIdx[r];
                        float* op = out + ((size_t)b * Ntot + orig) * CDIM
                                    + cc * 256 + wn + (lane & 3) * 2;
                        #pragma unroll
                        for (int tn = 0; tn < 8; ++tn) {
                            float2 v = make_float2(acc[tm][tn][half * 2],
                                                   acc[tm][tn][half * 2 + 1]);
                            *reinterpret_cast<float2*>(op + tn * 8) = v;
                        }
                    }
                }
            }
            if (g == 15) {
                #pragma unroll
                for (int tm = 0; tm < 2; ++tm)
                    #pragma unroll
                    for (int tn = 0; tn < 8; ++tn)
                        #pragma unroll
                        for (int q = 0; q < 4; ++q)
                            acc[tm][tn][q] = 0.0f;
            }
        }
    }
}

extern "C" void kernel_launch(void* const* d_in, const int* in_sizes, int n_in,
                              void* d_out, int out_size) {
    const float* points = (const float*)d_in[0];
    const float* lat    = (const float*)d_in[1];
    const float* eps    = (const float*)d_in[2];
    float* out = (float*)d_out;

    int B = in_sizes[1] / (G * CDIM);          // 4
    int N = in_sizes[0] / (3 * B);             // 50000
    int NCH = (N + 255) / 256;                 // 196

    cudaFuncSetAttribute(rbf_main, cudaFuncAttributeMaxDynamicSharedMemorySize, SM_TOTAL);

    rbf_prep<<<dim3(G, B), 256>>>(lat);
    rbf_histo<<<dim3(NCH, B), 256>>>(points, N);
    rbf_off<<<B, NCELL>>>(NCH);
    rbf_scatter<<<dim3(NCH, B), 256>>>(N);
    rbf_main<<<dim3((N + TILE_M - 1) / TILE_M, B), THREADS, SM_TOTAL>>>(points, eps, out, N);
}

// round 13
// speedup vs baseline: 1.2773x; 1.0080x over previous
#include <cuda_runtime.h>
#include <cuda_fp16.h>
#include <stdint.h>

#define G       512
#define CDIM    512
#define TILE_M  64
#define THREADS 256

// ---- SMEM layout (per CTA; 2 CTAs/SM) ----
#define SM_A       0                        // 64 x 1024B, XOR-swizzled
#define SM_BBASE   65536                    // 3 slots x (32 x 512B)
#define B_STAGE_SZ 16384
#define SM_QT      (SM_BBASE + 2 * B_STAGE_SZ)            // overlaid on slot 2
#define SM_CT      (SM_QT + 8192)
#define SM_PTS     (SM_BBASE + 3 * B_STAGE_SZ)            // 114688
#define SM_MBAR    (SM_PTS + 768)                         // 6 x 8B barriers
#define SM_TOTAL   (SM_MBAR + 64)                         // 115520 (x2 = 231040)

// fp16 image of latents: [b][k][c] row-major
__device__ __align__(16) unsigned char g_Bprep[4ull * G * CDIM * 2];

__device__ __forceinline__ uint32_t cvta_s(const void* p) {
    return (uint32_t)__cvta_generic_to_shared(const_cast<void*>(p));
}
__device__ __forceinline__ uint32_t pack_h2(float lo, float hi) {
    __half2 h = __floats2half2_rn(lo, hi);
    return *reinterpret_cast<uint32_t*>(&h);
}
__device__ __forceinline__ void ldsm_x4(uint32_t addr, uint32_t* r) {
    asm volatile("ldmatrix.sync.aligned.m8n8.x4.shared.b16 {%0,%1,%2,%3}, [%4];"
                 : "=r"(r[0]), "=r"(r[1]), "=r"(r[2]), "=r"(r[3]) : "r"(addr));
}
__device__ __forceinline__ void ldsm_x4_t(uint32_t addr, uint32_t* r) {
    asm volatile("ldmatrix.sync.aligned.m8n8.x4.trans.shared.b16 {%0,%1,%2,%3}, [%4];"
                 : "=r"(r[0]), "=r"(r[1]), "=r"(r[2]), "=r"(r[3]) : "r"(addr));
}
__device__ __forceinline__ void mma16816(float* d, const uint32_t* a, const uint32_t* b) {
    asm volatile(
        "mma.sync.aligned.m16n8k16.row.col.f32.f16.f16.f32 "
        "{%0,%1,%2,%3}, {%4,%5,%6,%7}, {%8,%9}, {%0,%1,%2,%3};"
        : "+f"(d[0]), "+f"(d[1]), "+f"(d[2]), "+f"(d[3])
        : "r"(a[0]), "r"(a[1]), "r"(a[2]), "r"(a[3]), "r"(b[0]), "r"(b[1]));
}
__device__ __forceinline__ void mbar_wait(uint32_t addr, uint32_t parity) {
    asm volatile(
        "{\n\t.reg .pred P;\n\t"
        "W_%=:\n\t"
        "mbarrier.try_wait.parity.acquire.cta.shared::cta.b64 P, [%0], %1, 0x989680;\n\t"
        "@!P bra W_%=;\n\t}"
        :: "r"(addr), "r"(parity) : "memory");
}
__device__ __forceinline__ void mbar_init(uint32_t addr, uint32_t cnt) {
    asm volatile("mbarrier.init.shared.b64 [%0], %1;" :: "r"(addr), "r"(cnt) : "memory");
}
__device__ __forceinline__ void mbar_arrive(uint32_t addr) {
    asm volatile("mbarrier.arrive.shared.b64 _, [%0];" :: "r"(addr) : "memory");
}
__device__ __forceinline__ void cpasync_arrive_noinc(uint32_t addr) {
    asm volatile("cp.async.mbarrier.arrive.noinc.shared::cta.b64 [%0];"
                 :: "r"(addr) : "memory");
}

// ---------- prep: elementwise fp32 -> fp16 convert of latents ----------
__global__ void rbf_prep(const float* __restrict__ lat) {
    int k = blockIdx.x, b = blockIdx.y;
    const float* src = lat + ((size_t)b * G + k) * CDIM;
    uint32_t* dst = (uint32_t*)(g_Bprep + ((size_t)b * G + k) * (CDIM * 2));
    int c2 = threadIdx.x;                   // 0..255
    dst[c2] = pack_h2(src[2 * c2], src[2 * c2 + 1]);
}

// ---------- main kernel ----------
__global__ void __launch_bounds__(THREADS, 2)
rbf_main(const float* __restrict__ points, const float* __restrict__ eps,
         float* __restrict__ out, int Ntot)
{
    extern __shared__ __align__(1024) unsigned char smem[];
    const uint32_t sbase = cvta_s(smem);
    const int tid  = threadIdx.x;
    const int wid  = tid >> 5;
    const int lane = tid & 31;
    const int b    = blockIdx.y;
    const int n0   = blockIdx.x * TILE_M;
    const unsigned char* Bsrc = g_Bprep + (size_t)b * (G * CDIM * 2);

    const uint32_t mb_full  = sbase + SM_MBAR;
    const uint32_t mb_empty = sbase + SM_MBAR + 24;

    if (tid == 0) {
        #pragma unroll
        for (int s = 0; s < 3; ++s) {
            mbar_init(mb_full + s * 8, 32);            // one producer WARP per slice
            mbar_init(mb_empty + s * 8, 8);            // one arrive per consumer warp
        }
    }
    __syncthreads();

    // warp-wide slice issue: 32 threads x 32 chunks (lane = column chunk, j = row)
    auto issue_slice_warp = [&](int g) {
        uint32_t dstbase = sbase + SM_BBASE + (uint32_t)(g % 3) * B_STAGE_SZ;
        int cc = g >> 4;
        const unsigned char* srow = Bsrc + ((size_t)((g & 15) * 32) * CDIM + cc * 256) * 2
                                    + (uint32_t)lane * 16;
        #pragma unroll 8
        for (int j = 0; j < 32; ++j) {
            const unsigned char* src = srow + (size_t)j * (CDIM * 2);
            uint32_t dst = dstbase + j * 512 + (uint32_t)((lane ^ (j & 7)) << 4);
            asm volatile("cp.async.cg.shared.global [%0], [%1], 16;" :: "r"(dst), "l"(src));
        }
    };

    // prefill: warp0 -> slice0, warp1 -> slice1
    if (wid == 0) { issue_slice_warp(0); cpasync_arrive_noinc(mb_full + 0); }
    if (wid == 1) { issue_slice_warp(1); cpasync_arrive_noinc(mb_full + 8); }

    // stage points
    {
        const float* psrc = points + ((size_t)b * Ntot + n0) * 3;
        int nfl = min(TILE_M, Ntot - n0) * 3;
        float* stage = (float*)(smem + SM_PTS);
        for (int i = tid; i < TILE_M * 3; i += THREADS)
            stage[i] = (i < nfl) ? psrc[i] : 0.0f;
    }

    // per-k tables (overlaid on slot-2 buffer; dead before slice 2 is filled)
    {
        float4* qt = (float4*)(smem + SM_QT);
        float*  ct = (float*)(smem + SM_CT);
        const float LOG2E = 1.4426950408889634f;
        const float step  = 2.0f / 7.0f;
        for (int k = tid; k < G; k += THREADS) {
            float gx = -1.0f + step * (float)(k >> 6);
            float gy = -1.0f + step * (float)((k >> 3) & 7);
            float gz = -1.0f + step * (float)(k & 7);
            float e  = eps[k];
            float s  = -e * e * LOG2E;
            qt[k] = make_float4(-2.0f * s * gx, -2.0f * s * gy, -2.0f * s * gz, s);
            ct[k] = s * (gx * gx + gy * gy + gz * gz);
        }
    }
    __syncthreads();

    // A-gen: thread -> (row = tid&63, kq = tid>>6), 128 exps -> swizzled fp16 SMEM
    {
        const int row   = tid & 63;
        const int kbase = (tid >> 6) * 128;
        const float* stage = (const float*)(smem + SM_PTS);
        float px = stage[row * 3 + 0], py = stage[row * 3 + 1], pz = stage[row * 3 + 2];
        float p2 = px * px + py * py + pz * pz;
        const float4* qt = (const float4*)(smem + SM_QT);
        const float*  ct = (const float*)(smem + SM_CT);
        const uint32_t arow = sbase + SM_A + (uint32_t)row * 1024;
        const int swz = row & 7;
        #pragma unroll 4
        for (int j = 0; j < 16; ++j) {
            float ev[8];
            #pragma unroll
            for (int q = 0; q < 8; ++q) {
                int k = kbase + j * 8 + q;
                float4 qv = qt[k];
                float arg = fmaf(qv.x, px, fmaf(qv.y, py,
                            fmaf(qv.z, pz, fmaf(qv.w, p2, ct[k]))));
                asm("ex2.approx.f32 %0, %1;" : "=f"(ev[q]) : "f"(arg));
            }
            uint4 pk;
            pk.x = pack_h2(ev[0], ev[1]);
            pk.y = pack_h2(ev[2], ev[3]);
            pk.z = pack_h2(ev[4], ev[5]);
            pk.w = pack_h2(ev[6], ev[7]);
            int cj = (kbase >> 3) + j;
            asm volatile("st.shared.v4.b32 [%0], {%1,%2,%3,%4};"
                         :: "r"(arow + (uint32_t)((cj ^ swz) << 4)),
                            "r"(pk.x), "r"(pk.y), "r"(pk.z), "r"(pk.w));
        }
    }
    __syncthreads();                       // A visible; tables dead; slice-2 fill may begin

    const int wm = (wid & 1) * 32;
    const int wn = (wid >> 1) * 64;
    const int hi = lane >> 4;

    // hoisted addressing
    uint32_t Abase[2], AswzX[2];
    #pragma unroll
    for (int tm = 0; tm < 2; ++tm) {
        int row = wm + tm * 16 + (lane & 15);
        Abase[tm] = sbase + SM_A + (uint32_t)row * 1024;
        AswzX[tm] = (uint32_t)(row & 7);
    }
    uint32_t Boff[2][4];
    #pragma unroll
    for (int kk = 0; kk < 2; ++kk)
        #pragma unroll
        for (int tn2 = 0; tn2 < 4; ++tn2) {
            int rr   = kk * 16 + (lane & 15);
            int colc = (wn + tn2 * 16 + hi * 8) >> 3;
            Boff[kk][tn2] = (uint32_t)rr * 512 + (uint32_t)((colc ^ (rr & 7)) << 4);
        }

    float acc[2][8][4];
    #pragma unroll
    for (int tm = 0; tm < 2; ++tm)
        #pragma unroll
        for (int tn = 0; tn < 8; ++tn)
            #pragma unroll
            for (int q = 0; q < 4; ++q)
                acc[tm][tn][q] = 0.0f;

    for (int g = 0; g < 32; ++g) {
        const int slot = g % 3;
        mbar_wait(mb_full + slot * 8, (uint32_t)((g / 3) & 1));

        uint32_t Bb = sbase + SM_BBASE + (uint32_t)slot * B_STAGE_SZ;
        uint32_t c0 = (uint32_t)((g & 15) * 4 + hi);
        #pragma unroll
        for (int kk = 0; kk < 2; ++kk) {
            uint32_t af[2][4];
            #pragma unroll
            for (int tm = 0; tm < 2; ++tm)
                ldsm_x4(Abase[tm] + (((c0 + kk * 2) ^ AswzX[tm]) << 4), af[tm]);
            uint32_t bf[4][4];
            #pragma unroll
            for (int tn2 = 0; tn2 < 4; ++tn2)
                ldsm_x4_t(Bb + Boff[kk][tn2], bf[tn2]);
            #pragma unroll
            for (int tm = 0; tm < 2; ++tm)
                #pragma unroll
                for (int tn = 0; tn < 8; ++tn)
                    mma16816(acc[tm][tn], af[tm], &bf[tn >> 1][(tn & 1) * 2]);
        }

        if (lane == 0) mbar_arrive(mb_empty + slot * 8);     // this warp consumed slice g

        // rotating designated producer: warp (g+2)&7 alone issues slice g+2
        if (g + 2 < 32 && wid == ((g + 2) & 7)) {
            if (g >= 1)   // slot (g+2)%3 last used by slice g-1; wait all 8 consumed it
                mbar_wait(mb_empty + ((g - 1) % 3) * 8, (uint32_t)(((g - 1) / 3) & 1));
            issue_slice_warp(g + 2);
            cpasync_arrive_noinc(mb_full + ((g + 2) % 3) * 8);
        }

        if (g == 15 || g == 31) {
            int cc = g >> 4;
            #pragma unroll
            for (int tm = 0; tm < 2; ++tm) {
                int rbase = n0 + wm + tm * 16 + (lane >> 2);
                #pragma unroll
                for (int half = 0; half < 2; ++half) {
                    int r = rbase + half * 8;
                    if (r < Ntot) {
                        float* op = out + ((size_t)b * Ntot + r) * CDIM
                                    + cc * 256 + wn + (lane & 3) * 2;
                        #pragma unroll
                        for (int tn = 0; tn < 8; ++tn) {
                            float2 v = make_float2(acc[tm][tn][half * 2],
                                                   acc[tm][tn][half * 2 + 1]);
                            *reinterpret_cast<float2*>(op + tn * 8) = v;
                        }
                    }
                }
            }
            if (g == 15) {
                #pragma unroll
                for (int tm = 0; tm < 2; ++tm)
                    #pragma unroll
                    for (int tn = 0; tn < 8; ++tn)
                        #pragma unroll
                        for (int q = 0; q < 4; ++q)
                            acc[tm][tn][q] = 0.0f;
            }
        }
    }
}

extern "C" void kernel_launch(void* const* d_in, const int* in_sizes, int n_in,
                              void* d_out, int out_size) {
    const float* points = (const float*)d_in[0];
    const float* lat    = (const float*)d_in[1];
    const float* eps    = (const float*)d_in[2];
    float* out = (float*)d_out;

    int B = in_sizes[1] / (G * CDIM);          // 4
    int N = in_sizes[0] / (3 * B);             // 50000

    cudaFuncSetAttribute(rbf_main, cudaFuncAttributeMaxDynamicSharedMemorySize, SM_TOTAL);

    rbf_prep<<<dim3(G, B), 256>>>(lat);
    rbf_main<<<dim3((N + TILE_M - 1) / TILE_M, B), THREADS, SM_TOTAL>>>(points, eps, out, N);
}